// round 1
// baseline (speedup 1.0000x reference)
#include <cuda_runtime.h>

#define N_NODES 20000
#define N_EDGES 320000
#define IN_FEATS 64
#define DOUT 128
#define KMIX 4
#define HPW (KMIX * DOUT)   // 512

// Scratch (no allocation allowed): hp buffer + two intermediate h buffers
__device__ float g_hp[N_NODES * HPW];    // 40.96 MB
__device__ float g_h0[N_NODES * DOUT];   // 10.24 MB
__device__ float g_h1[N_NODES * DOUT];   // 10.24 MB

// ---------------------------------------------------------------------------
// GEMM: C[M, N] = A[M, Kdim] @ B[Kdim, N]   (row-major, fp32)
// BM=64, BN=64, BK=16, 256 threads, 4x4 per thread.
// ---------------------------------------------------------------------------
#define BM 64
#define BN 64
#define BKT 16

__global__ __launch_bounds__(256) void gemm_kernel(
    const float* __restrict__ A, const float* __restrict__ B,
    float* __restrict__ C, int M, int Kdim, int N)
{
    __shared__ float As[BKT][BM];
    __shared__ float Bs[BKT][BN];

    const int tid = threadIdx.x;
    const int tx = tid % 16;          // column group
    const int ty = tid / 16;          // row group
    const int row0 = blockIdx.y * BM;
    const int col0 = blockIdx.x * BN;

    float acc[4][4] = {};

    for (int kb = 0; kb < Kdim; kb += BKT) {
        // Load A tile (BM x BKT) -> As[k][m]
        #pragma unroll
        for (int i = tid; i < BM * BKT; i += 256) {
            int m = i / BKT;
            int k = i % BKT;
            int gr = row0 + m;
            As[k][m] = (gr < M) ? A[(size_t)gr * Kdim + kb + k] : 0.0f;
        }
        // Load B tile (BKT x BN) -> Bs[k][n]
        #pragma unroll
        for (int i = tid; i < BKT * BN; i += 256) {
            int k = i / BN;
            int n = i % BN;
            Bs[k][n] = B[(size_t)(kb + k) * N + col0 + n];
        }
        __syncthreads();

        #pragma unroll
        for (int k = 0; k < BKT; k++) {
            float a[4], b[4];
            #pragma unroll
            for (int i = 0; i < 4; i++) a[i] = As[k][ty * 4 + i];
            #pragma unroll
            for (int j = 0; j < 4; j++) b[j] = Bs[k][tx * 4 + j];
            #pragma unroll
            for (int i = 0; i < 4; i++)
                #pragma unroll
                for (int j = 0; j < 4; j++)
                    acc[i][j] += a[i] * b[j];
        }
        __syncthreads();
    }

    #pragma unroll
    for (int i = 0; i < 4; i++) {
        int gr = row0 + ty * 4 + i;
        if (gr < M) {
            float4 v = make_float4(acc[i][0], acc[i][1], acc[i][2], acc[i][3]);
            *(float4*)(C + (size_t)gr * N + col0 + tx * 4) = v;
        }
    }
}

// ---------------------------------------------------------------------------
// Init output buffer to broadcast bias: out[n, o] = bias[o]
// ---------------------------------------------------------------------------
__global__ void init_bias_kernel(float* __restrict__ out,
                                 const float* __restrict__ bias)
{
    int i = blockIdx.x * 256 + threadIdx.x;
    if (i < N_NODES * DOUT) out[i] = bias[i & (DOUT - 1)];
}

// ---------------------------------------------------------------------------
// Edge kernel: one warp per edge.
//   w[k] = exp(-0.5 * || (tanh(p @ pw + pb) - mu_k) * inv_sigma_k ||^2)
//   msg  = sum_k w[k] * hp[src, k, :]
//   atomicAdd(out[dst, :], msg)
// Lane l owns outputs [4l, 4l+4) via float4.
// ---------------------------------------------------------------------------
__global__ __launch_bounds__(256) void edge_kernel(
    const float* __restrict__ hp,
    const float* __restrict__ pseudo,
    const int* __restrict__ src,
    const int* __restrict__ dst,
    const float* __restrict__ mu,
    const float* __restrict__ inv_sigma,
    const float* __restrict__ pw,
    const float* __restrict__ pb,
    float* __restrict__ out)
{
    const int e = blockIdx.x * 8 + (threadIdx.x >> 5);
    if (e >= N_EDGES) return;
    const int lane = threadIdx.x & 31;

    const float p0 = __ldg(&pseudo[2 * e + 0]);
    const float p1 = __ldg(&pseudo[2 * e + 1]);
    const float u0 = tanhf(p0 * pw[0] + p1 * pw[2] + pb[0]);
    const float u1 = tanhf(p0 * pw[1] + p1 * pw[3] + pb[1]);

    float w[KMIX];
    #pragma unroll
    for (int k = 0; k < KMIX; k++) {
        float d0 = (u0 - mu[2 * k + 0]) * inv_sigma[2 * k + 0];
        float d1 = (u1 - mu[2 * k + 1]) * inv_sigma[2 * k + 1];
        w[k] = __expf(-0.5f * (d0 * d0 + d1 * d1));
    }

    const int s = src[e];
    const float4* hpr = (const float4*)(hp + (size_t)s * HPW) + lane;

    float4 acc = make_float4(0.f, 0.f, 0.f, 0.f);
    #pragma unroll
    for (int k = 0; k < KMIX; k++) {
        float4 v = __ldg(hpr + k * 32);
        acc.x += w[k] * v.x;
        acc.y += w[k] * v.y;
        acc.z += w[k] * v.z;
        acc.w += w[k] * v.w;
    }

    float* o = out + (size_t)dst[e] * DOUT + lane * 4;
    atomicAdd(o + 0, acc.x);
    atomicAdd(o + 1, acc.y);
    atomicAdd(o + 2, acc.z);
    atomicAdd(o + 3, acc.w);
}

// ---------------------------------------------------------------------------
// Launch: 3 layers, each = GEMM -> bias-init -> edge scatter
// ---------------------------------------------------------------------------
extern "C" void kernel_launch(void* const* d_in, const int* in_sizes, int n_in,
                              void* d_out, int out_size)
{
    const float* features = (const float*)d_in[0];
    const float* pseudo   = (const float*)d_in[1];
    const int*   src      = (const int*)d_in[2];
    const int*   dst      = (const int*)d_in[3];

    // per-layer params start at 4, stride 6: fc_w, mu, inv_sigma, bias, pw, pb
    const float* fc_w[3];
    const float* mu[3];
    const float* is[3];
    const float* bias[3];
    const float* pw[3];
    const float* pb[3];
    for (int l = 0; l < 3; l++) {
        fc_w[l] = (const float*)d_in[4 + 6 * l + 0];
        mu[l]   = (const float*)d_in[4 + 6 * l + 1];
        is[l]   = (const float*)d_in[4 + 6 * l + 2];
        bias[l] = (const float*)d_in[4 + 6 * l + 3];
        pw[l]   = (const float*)d_in[4 + 6 * l + 4];
        pb[l]   = (const float*)d_in[4 + 6 * l + 5];
    }

    float* hp;
    float* h0;
    float* h1;
    cudaGetSymbolAddress((void**)&hp, g_hp);
    cudaGetSymbolAddress((void**)&h0, g_h0);
    cudaGetSymbolAddress((void**)&h1, g_h1);

    const float* layer_in[3]  = { features, h0, h1 };
    float*       layer_out[3] = { h0, h1, (float*)d_out };
    const int    layer_k[3]   = { IN_FEATS, DOUT, DOUT };

    dim3 gemm_grid(HPW / BN, (N_NODES + BM - 1) / BM);
    const int init_blocks = (N_NODES * DOUT + 255) / 256;
    const int edge_blocks = (N_EDGES + 7) / 8;

    for (int l = 0; l < 3; l++) {
        gemm_kernel<<<gemm_grid, 256>>>(layer_in[l], fc_w[l], hp,
                                        N_NODES, layer_k[l], HPW);
        init_bias_kernel<<<init_blocks, 256>>>(layer_out[l], bias[l]);
        edge_kernel<<<edge_blocks, 256>>>(hp, pseudo, src, dst,
                                          mu[l], is[l], pw[l], pb[l],
                                          layer_out[l]);
    }
}

// round 4
// speedup vs baseline: 1.5808x; 1.5808x over previous
#include <cuda_runtime.h>

#define N_NODES 20000
#define N_EDGES 320000
#define IN_FEATS 64
#define DOUT 128
#define KMIX 4
#define HPW (KMIX * DOUT)   // 512

// Scratch (no allocation allowed)
__device__ float g_hp[N_NODES * HPW];    // 40.96 MB
__device__ float g_h0[N_NODES * DOUT];   // 10.24 MB
__device__ float g_h1[N_NODES * DOUT];   // 10.24 MB

// ---------------------------------------------------------------------------
// GEMM: C[M, N] = A[M, Kdim] @ B[Kdim, N]   (row-major, fp32)
// 128x128 block tile, BK=16, 256 threads, 8x8 per thread (4+4 split halves).
// ---------------------------------------------------------------------------
#define GBM 128
#define GBN 128
#define GBK 16

__global__ __launch_bounds__(256) void gemm_kernel(
    const float* __restrict__ A, const float* __restrict__ B,
    float* __restrict__ C, int M, int Kdim, int N)
{
    __shared__ float As[GBK][GBM];
    __shared__ float Bs[GBK][GBN];

    const int tid = threadIdx.x;
    const int tx = tid & 15;          // 0..15 column group
    const int ty = tid >> 4;          // 0..15 row group
    const int row0 = blockIdx.y * GBM;
    const int col0 = blockIdx.x * GBN;

    float acc[8][8] = {};

    for (int kb = 0; kb < Kdim; kb += GBK) {
        // A tile: 128 rows x 16 k = 512 float4 loads. f: r=f>>2, kq=(f&3)*4
        #pragma unroll
        for (int f = tid; f < 512; f += 256) {
            int r  = f >> 2;
            int kq = (f & 3) << 2;
            int gr = row0 + r;
            float4 v = make_float4(0.f, 0.f, 0.f, 0.f);
            if (gr < M)
                v = *(const float4*)&A[(size_t)gr * Kdim + kb + kq];
            As[kq + 0][r] = v.x;
            As[kq + 1][r] = v.y;
            As[kq + 2][r] = v.z;
            As[kq + 3][r] = v.w;
        }
        // B tile: 16 rows x 128 cols = 512 float4 loads. f: r=f>>5, c=(f&31)*4
        #pragma unroll
        for (int f = tid; f < 512; f += 256) {
            int r = f >> 5;
            int c = (f & 31) << 2;
            *(float4*)&Bs[r][c] =
                *(const float4*)&B[(size_t)(kb + r) * N + col0 + c];
        }
        __syncthreads();

        #pragma unroll
        for (int k = 0; k < GBK; k++) {
            float a[8], b[8];
            *(float4*)&a[0] = *(const float4*)&As[k][ty * 4];
            *(float4*)&a[4] = *(const float4*)&As[k][64 + ty * 4];
            *(float4*)&b[0] = *(const float4*)&Bs[k][tx * 4];
            *(float4*)&b[4] = *(const float4*)&Bs[k][64 + tx * 4];
            #pragma unroll
            for (int i = 0; i < 8; i++)
                #pragma unroll
                for (int j = 0; j < 8; j++)
                    acc[i][j] += a[i] * b[j];
        }
        __syncthreads();
    }

    #pragma unroll
    for (int half = 0; half < 2; half++) {
        #pragma unroll
        for (int i = 0; i < 4; i++) {
            int gr = row0 + half * 64 + ty * 4 + i;
            if (gr < M) {
                float* crow = C + (size_t)gr * N + col0;
                *(float4*)&crow[tx * 4] =
                    make_float4(acc[half * 4 + i][0], acc[half * 4 + i][1],
                                acc[half * 4 + i][2], acc[half * 4 + i][3]);
                *(float4*)&crow[64 + tx * 4] =
                    make_float4(acc[half * 4 + i][4], acc[half * 4 + i][5],
                                acc[half * 4 + i][6], acc[half * 4 + i][7]);
            }
        }
    }
}

// ---------------------------------------------------------------------------
// Init output buffer to broadcast bias: out[n, o] = bias[o]  (float4)
// ---------------------------------------------------------------------------
__global__ void init_bias_kernel(float4* __restrict__ out,
                                 const float4* __restrict__ bias)
{
    int i = blockIdx.x * 256 + threadIdx.x;
    if (i < N_NODES * (DOUT / 4)) out[i] = bias[i & (DOUT / 4 - 1)];
}

// ---------------------------------------------------------------------------
// Edge kernel: one warp per edge; vector red.global.add.v4.f32 scatter.
// ---------------------------------------------------------------------------
__global__ __launch_bounds__(256) void edge_kernel(
    const float* __restrict__ hp,
    const float* __restrict__ pseudo,
    const int* __restrict__ src,
    const int* __restrict__ dst,
    const float* __restrict__ mu,
    const float* __restrict__ inv_sigma,
    const float* __restrict__ pw,
    const float* __restrict__ pb,
    float* __restrict__ out)
{
    const int e = blockIdx.x * 8 + (threadIdx.x >> 5);
    if (e >= N_EDGES) return;
    const int lane = threadIdx.x & 31;

    const int s = src[e];
    const int d = dst[e];

    const float p0 = __ldg(&pseudo[2 * e + 0]);
    const float p1 = __ldg(&pseudo[2 * e + 1]);
    const float u0 = tanhf(p0 * pw[0] + p1 * pw[2] + pb[0]);
    const float u1 = tanhf(p0 * pw[1] + p1 * pw[3] + pb[1]);

    float w[KMIX];
    #pragma unroll
    for (int k = 0; k < KMIX; k++) {
        float d0 = (u0 - mu[2 * k + 0]) * inv_sigma[2 * k + 0];
        float d1 = (u1 - mu[2 * k + 1]) * inv_sigma[2 * k + 1];
        w[k] = __expf(-0.5f * (d0 * d0 + d1 * d1));
    }

    const float4* hpr = (const float4*)(hp + (size_t)s * HPW) + lane;

    float4 acc = make_float4(0.f, 0.f, 0.f, 0.f);
    #pragma unroll
    for (int k = 0; k < KMIX; k++) {
        float4 v = __ldg(hpr + k * 32);
        acc.x += w[k] * v.x;
        acc.y += w[k] * v.y;
        acc.z += w[k] * v.z;
        acc.w += w[k] * v.w;
    }

    float* o = out + (size_t)d * DOUT + lane * 4;
    asm volatile("red.global.add.v4.f32 [%0], {%1, %2, %3, %4};"
                 :: "l"(o), "f"(acc.x), "f"(acc.y), "f"(acc.z), "f"(acc.w)
                 : "memory");
}

// ---------------------------------------------------------------------------
// Launch: 3 layers, each = GEMM -> bias-init -> edge scatter
// ---------------------------------------------------------------------------
extern "C" void kernel_launch(void* const* d_in, const int* in_sizes, int n_in,
                              void* d_out, int out_size)
{
    const float* features = (const float*)d_in[0];
    const float* pseudo   = (const float*)d_in[1];
    const int*   src      = (const int*)d_in[2];
    const int*   dst      = (const int*)d_in[3];

    const float* fc_w[3];
    const float* mu[3];
    const float* is[3];
    const float* bias[3];
    const float* pw[3];
    const float* pb[3];
    for (int l = 0; l < 3; l++) {
        fc_w[l] = (const float*)d_in[4 + 6 * l + 0];
        mu[l]   = (const float*)d_in[4 + 6 * l + 1];
        is[l]   = (const float*)d_in[4 + 6 * l + 2];
        bias[l] = (const float*)d_in[4 + 6 * l + 3];
        pw[l]   = (const float*)d_in[4 + 6 * l + 4];
        pb[l]   = (const float*)d_in[4 + 6 * l + 5];
    }

    float* hp; float* h0; float* h1;
    cudaGetSymbolAddress((void**)&hp, g_hp);
    cudaGetSymbolAddress((void**)&h0, g_h0);
    cudaGetSymbolAddress((void**)&h1, g_h1);

    const float* layer_in[3]  = { features, h0, h1 };
    float*       layer_out[3] = { h0, h1, (float*)d_out };
    const int    layer_k[3]   = { IN_FEATS, DOUT, DOUT };

    dim3 gemm_grid(HPW / GBN, (N_NODES + GBM - 1) / GBM);
    const int init_blocks = (N_NODES * (DOUT / 4) + 255) / 256;
    const int edge_blocks = (N_EDGES + 7) / 8;

    for (int l = 0; l < 3; l++) {
        gemm_kernel<<<gemm_grid, 256>>>(layer_in[l], fc_w[l], hp,
                                        N_NODES, layer_k[l], HPW);
        init_bias_kernel<<<init_blocks, 256>>>((float4*)layer_out[l],
                                               (const float4*)bias[l]);
        edge_kernel<<<edge_blocks, 256>>>(hp, pseudo, src, dst,
                                          mu[l], is[l], pw[l], pb[l],
                                          layer_out[l]);
    }
}

// round 5
// speedup vs baseline: 1.6914x; 1.0700x over previous
#include <cuda_runtime.h>
#include <cuda_fp16.h>

#define N_NODES 20000
#define N_EDGES 320000
#define IN_FEATS 64
#define DOUT 128
#define KMIX 4
#define HPW (KMIX * DOUT)   // 512

// Scratch (no allocation allowed)
__device__ __half g_hp[N_NODES * HPW];   // 20.48 MB (fp16) — L2-resident
__device__ float  g_h0[N_NODES * DOUT];  // 10.24 MB
__device__ float  g_h1[N_NODES * DOUT];  // 10.24 MB

// ---------------------------------------------------------------------------
// GEMM: C[M, N] = A[M, Kdim] @ B[Kdim, N]   (A,B fp32, accum fp32, C fp16)
// 128x128 block tile, BK=16, 256 threads, 8x8 per thread (4+4 split halves).
// ---------------------------------------------------------------------------
#define GBM 128
#define GBN 128
#define GBK 16

__device__ __forceinline__ uint2 f4_to_h4(float a, float b, float c, float d)
{
    __half2 lo = __float22half2_rn(make_float2(a, b));
    __half2 hi = __float22half2_rn(make_float2(c, d));
    uint2 r;
    r.x = *(unsigned int*)&lo;
    r.y = *(unsigned int*)&hi;
    return r;
}

__global__ __launch_bounds__(256) void gemm_kernel(
    const float* __restrict__ A, const float* __restrict__ B,
    __half* __restrict__ C, int M, int Kdim, int N)
{
    __shared__ float As[GBK][GBM];
    __shared__ float Bs[GBK][GBN];

    const int tid = threadIdx.x;
    const int tx = tid & 15;          // 0..15 column group
    const int ty = tid >> 4;          // 0..15 row group
    const int row0 = blockIdx.y * GBM;
    const int col0 = blockIdx.x * GBN;

    float acc[8][8] = {};

    for (int kb = 0; kb < Kdim; kb += GBK) {
        // A tile: 128 rows x 16 k = 512 float4 loads. f: r=f>>2, kq=(f&3)*4
        #pragma unroll
        for (int f = tid; f < 512; f += 256) {
            int r  = f >> 2;
            int kq = (f & 3) << 2;
            int gr = row0 + r;
            float4 v = make_float4(0.f, 0.f, 0.f, 0.f);
            if (gr < M)
                v = *(const float4*)&A[(size_t)gr * Kdim + kb + kq];
            As[kq + 0][r] = v.x;
            As[kq + 1][r] = v.y;
            As[kq + 2][r] = v.z;
            As[kq + 3][r] = v.w;
        }
        // B tile: 16 rows x 128 cols = 512 float4 loads. f: r=f>>5, c=(f&31)*4
        #pragma unroll
        for (int f = tid; f < 512; f += 256) {
            int r = f >> 5;
            int c = (f & 31) << 2;
            *(float4*)&Bs[r][c] =
                *(const float4*)&B[(size_t)(kb + r) * N + col0 + c];
        }
        __syncthreads();

        #pragma unroll
        for (int k = 0; k < GBK; k++) {
            float a[8], b[8];
            *(float4*)&a[0] = *(const float4*)&As[k][ty * 4];
            *(float4*)&a[4] = *(const float4*)&As[k][64 + ty * 4];
            *(float4*)&b[0] = *(const float4*)&Bs[k][tx * 4];
            *(float4*)&b[4] = *(const float4*)&Bs[k][64 + tx * 4];
            #pragma unroll
            for (int i = 0; i < 8; i++)
                #pragma unroll
                for (int j = 0; j < 8; j++)
                    acc[i][j] += a[i] * b[j];
        }
        __syncthreads();
    }

    // Epilogue: convert fp32 acc -> fp16, store 4 halves (uint2) per segment
    #pragma unroll
    for (int half_ = 0; half_ < 2; half_++) {
        #pragma unroll
        for (int i = 0; i < 4; i++) {
            int gr = row0 + half_ * 64 + ty * 4 + i;
            if (gr < M) {
                __half* crow = C + (size_t)gr * N + col0;
                *(uint2*)&crow[tx * 4] =
                    f4_to_h4(acc[half_ * 4 + i][0], acc[half_ * 4 + i][1],
                             acc[half_ * 4 + i][2], acc[half_ * 4 + i][3]);
                *(uint2*)&crow[64 + tx * 4] =
                    f4_to_h4(acc[half_ * 4 + i][4], acc[half_ * 4 + i][5],
                             acc[half_ * 4 + i][6], acc[half_ * 4 + i][7]);
            }
        }
    }
}

// ---------------------------------------------------------------------------
// Init output buffer to broadcast bias: out[n, o] = bias[o]  (float4)
// ---------------------------------------------------------------------------
__global__ void init_bias_kernel(float4* __restrict__ out,
                                 const float4* __restrict__ bias)
{
    int i = blockIdx.x * 256 + threadIdx.x;
    if (i < N_NODES * (DOUT / 4)) out[i] = bias[i & (DOUT / 4 - 1)];
}

// ---------------------------------------------------------------------------
// Edge kernel: one warp per edge; fp16 gather (half traffic), fp32 math,
// vector red.global.add.v4.f32 scatter.
// ---------------------------------------------------------------------------
__global__ __launch_bounds__(256) void edge_kernel(
    const __half* __restrict__ hp,
    const float* __restrict__ pseudo,
    const int* __restrict__ src,
    const int* __restrict__ dst,
    const float* __restrict__ mu,
    const float* __restrict__ inv_sigma,
    const float* __restrict__ pw,
    const float* __restrict__ pb,
    float* __restrict__ out)
{
    const int e = blockIdx.x * 8 + (threadIdx.x >> 5);
    if (e >= N_EDGES) return;
    const int lane = threadIdx.x & 31;

    const int s = src[e];
    const int d = dst[e];

    const float p0 = __ldg(&pseudo[2 * e + 0]);
    const float p1 = __ldg(&pseudo[2 * e + 1]);
    const float u0 = tanhf(p0 * pw[0] + p1 * pw[2] + pb[0]);
    const float u1 = tanhf(p0 * pw[1] + p1 * pw[3] + pb[1]);

    float w[KMIX];
    #pragma unroll
    for (int k = 0; k < KMIX; k++) {
        float d0 = (u0 - mu[2 * k + 0]) * inv_sigma[2 * k + 0];
        float d1 = (u1 - mu[2 * k + 1]) * inv_sigma[2 * k + 1];
        w[k] = __expf(-0.5f * (d0 * d0 + d1 * d1));
    }

    // lane owns output cols [4*lane, 4*lane+4). Per k: 8-byte (4-half) load.
    const __half* hpb = hp + (size_t)s * HPW + lane * 4;

    float4 acc = make_float4(0.f, 0.f, 0.f, 0.f);
    #pragma unroll
    for (int k = 0; k < KMIX; k++) {
        uint2 raw = __ldg((const uint2*)(hpb + k * DOUT));
        __half2 h01 = *(__half2*)&raw.x;
        __half2 h23 = *(__half2*)&raw.y;
        float2 f01 = __half22float2(h01);
        float2 f23 = __half22float2(h23);
        acc.x += w[k] * f01.x;
        acc.y += w[k] * f01.y;
        acc.z += w[k] * f23.x;
        acc.w += w[k] * f23.y;
    }

    float* o = out + (size_t)d * DOUT + lane * 4;
    asm volatile("red.global.add.v4.f32 [%0], {%1, %2, %3, %4};"
                 :: "l"(o), "f"(acc.x), "f"(acc.y), "f"(acc.z), "f"(acc.w)
                 : "memory");
}

// ---------------------------------------------------------------------------
// Launch: 3 layers, each = GEMM -> bias-init -> edge scatter
// ---------------------------------------------------------------------------
extern "C" void kernel_launch(void* const* d_in, const int* in_sizes, int n_in,
                              void* d_out, int out_size)
{
    const float* features = (const float*)d_in[0];
    const float* pseudo   = (const float*)d_in[1];
    const int*   src      = (const int*)d_in[2];
    const int*   dst      = (const int*)d_in[3];

    const float* fc_w[3];
    const float* mu[3];
    const float* is[3];
    const float* bias[3];
    const float* pw[3];
    const float* pb[3];
    for (int l = 0; l < 3; l++) {
        fc_w[l] = (const float*)d_in[4 + 6 * l + 0];
        mu[l]   = (const float*)d_in[4 + 6 * l + 1];
        is[l]   = (const float*)d_in[4 + 6 * l + 2];
        bias[l] = (const float*)d_in[4 + 6 * l + 3];
        pw[l]   = (const float*)d_in[4 + 6 * l + 4];
        pb[l]   = (const float*)d_in[4 + 6 * l + 5];
    }

    __half* hp; float* h0; float* h1;
    cudaGetSymbolAddress((void**)&hp, g_hp);
    cudaGetSymbolAddress((void**)&h0, g_h0);
    cudaGetSymbolAddress((void**)&h1, g_h1);

    const float* layer_in[3]  = { features, h0, h1 };
    float*       layer_out[3] = { h0, h1, (float*)d_out };
    const int    layer_k[3]   = { IN_FEATS, DOUT, DOUT };

    dim3 gemm_grid(HPW / GBN, (N_NODES + GBM - 1) / GBM);
    const int init_blocks = (N_NODES * (DOUT / 4) + 255) / 256;
    const int edge_blocks = (N_EDGES + 7) / 8;

    for (int l = 0; l < 3; l++) {
        gemm_kernel<<<gemm_grid, 256>>>(layer_in[l], fc_w[l], hp,
                                        N_NODES, layer_k[l], HPW);
        init_bias_kernel<<<init_blocks, 256>>>((float4*)layer_out[l],
                                               (const float4*)bias[l]);
        edge_kernel<<<edge_blocks, 256>>>(hp, pseudo, src, dst,
                                          mu[l], is[l], pw[l], pb[l],
                                          layer_out[l]);
    }
}

// round 7
// speedup vs baseline: 1.7230x; 1.0187x over previous
#include <cuda_runtime.h>
#include <cuda_fp16.h>
#include <mma.h>

using namespace nvcuda;

#define N_NODES 20000
#define N_EDGES 320000
#define IN_FEATS 64
#define DOUT 128
#define KMIX 4
#define HPW (KMIX * DOUT)   // 512

// Scratch (no allocation allowed)
__device__ __half g_hp[N_NODES * HPW];   // 20.48 MB (fp16) — L2-resident
__device__ float  g_h0[N_NODES * DOUT];  // 10.24 MB
__device__ float  g_h1[N_NODES * DOUT];  // 10.24 MB

// ---------------------------------------------------------------------------
// tf32 tensor-core GEMM: C[M,N] = A[M,Kdim] @ B[Kdim,N], fp32 in, fp16 out.
// Block tile 128x128, BK=32. 8 warps: warp_row (0..3) x warp_col (0..1),
// each warp owns 32x64 = 2x4 wmma 16x16x8 fragments. fp32 accumulate.
// ---------------------------------------------------------------------------
#define TBM 128
#define TBN 128
#define TBK 32
#define A_LD 36    // 32 + 4 pad
#define B_LD 132   // 128 + 4 pad

__global__ __launch_bounds__(256) void gemm_tf32_kernel(
    const float* __restrict__ A, const float* __restrict__ B,
    __half* __restrict__ C, int M, int Kdim, int N)
{
    __shared__ float As[TBM][A_LD];      // 18432 B
    __shared__ float Bs[TBK][B_LD];      // 16896 B
    __shared__ float stage[8][16 * 16];  //  8192 B

    const int tid = threadIdx.x;
    const int wid = tid >> 5;
    const int lane = tid & 31;
    const int warp_row = wid >> 1;   // 0..3 -> rows 32*warp_row
    const int warp_col = wid & 1;    // 0..1 -> cols 64*warp_col
    const int row0 = blockIdx.y * TBM;
    const int col0 = blockIdx.x * TBN;

    wmma::fragment<wmma::accumulator, 16, 16, 8, float> acc[2][4];
    #pragma unroll
    for (int i = 0; i < 2; i++)
        #pragma unroll
        for (int j = 0; j < 4; j++)
            wmma::fill_fragment(acc[i][j], 0.0f);

    for (int kb = 0; kb < Kdim; kb += TBK) {
        // A tile: 128 x 32 floats = 1024 float4. f: r=f>>3, c=(f&7)*4
        #pragma unroll
        for (int f = tid; f < 1024; f += 256) {
            int r = f >> 3;
            int c = (f & 7) << 2;
            int gr = row0 + r;
            float4 v = make_float4(0.f, 0.f, 0.f, 0.f);
            if (gr < M)
                v = *(const float4*)&A[(size_t)gr * Kdim + kb + c];
            As[r][c + 0] = v.x;
            As[r][c + 1] = v.y;
            As[r][c + 2] = v.z;
            As[r][c + 3] = v.w;
        }
        // B tile: 32 x 128 floats = 1024 float4. f: r=f>>5, c=(f&31)*4
        #pragma unroll
        for (int f = tid; f < 1024; f += 256) {
            int r = f >> 5;
            int c = (f & 31) << 2;
            float4 v = *(const float4*)&B[(size_t)(kb + r) * N + col0 + c];
            Bs[r][c + 0] = v.x;
            Bs[r][c + 1] = v.y;
            Bs[r][c + 2] = v.z;
            Bs[r][c + 3] = v.w;
        }
        __syncthreads();

        #pragma unroll
        for (int kk = 0; kk < TBK / 8; kk++) {
            wmma::fragment<wmma::matrix_a, 16, 16, 8,
                           wmma::precision::tf32, wmma::row_major> af[2];
            wmma::fragment<wmma::matrix_b, 16, 16, 8,
                           wmma::precision::tf32, wmma::row_major> bf[4];
            #pragma unroll
            for (int i = 0; i < 2; i++) {
                wmma::load_matrix_sync(
                    af[i], &As[warp_row * 32 + i * 16][kk * 8], A_LD);
                #pragma unroll
                for (int t = 0; t < af[i].num_elements; t++)
                    af[i].x[t] = wmma::__float_to_tf32(af[i].x[t]);
            }
            #pragma unroll
            for (int j = 0; j < 4; j++) {
                wmma::load_matrix_sync(
                    bf[j], &Bs[kk * 8][warp_col * 64 + j * 16], B_LD);
                #pragma unroll
                for (int t = 0; t < bf[j].num_elements; t++)
                    bf[j].x[t] = wmma::__float_to_tf32(bf[j].x[t]);
            }
            #pragma unroll
            for (int i = 0; i < 2; i++)
                #pragma unroll
                for (int j = 0; j < 4; j++)
                    wmma::mma_sync(acc[i][j], af[i], bf[j], acc[i][j]);
        }
        __syncthreads();
    }

    // Epilogue: fragment -> SMEM stage -> fp16 uint4 store
    #pragma unroll
    for (int i = 0; i < 2; i++) {
        #pragma unroll
        for (int j = 0; j < 4; j++) {
            wmma::store_matrix_sync(stage[wid], acc[i][j], 16,
                                    wmma::mem_row_major);
            __syncwarp();
            int r = lane >> 1;            // 0..15
            int coff = (lane & 1) << 3;   // 0 or 8
            int gr = row0 + warp_row * 32 + i * 16 + r;
            if (gr < M) {
                const float* srow = &stage[wid][r * 16 + coff];
                __half2 h0 = __float22half2_rn(make_float2(srow[0], srow[1]));
                __half2 h1 = __float22half2_rn(make_float2(srow[2], srow[3]));
                __half2 h2 = __float22half2_rn(make_float2(srow[4], srow[5]));
                __half2 h3 = __float22half2_rn(make_float2(srow[6], srow[7]));
                uint4 v;
                v.x = *(unsigned int*)&h0;
                v.y = *(unsigned int*)&h1;
                v.z = *(unsigned int*)&h2;
                v.w = *(unsigned int*)&h3;
                *(uint4*)&C[(size_t)gr * N + col0 + warp_col * 64 + j * 16 + coff] = v;
            }
            __syncwarp();
        }
    }
}

// ---------------------------------------------------------------------------
// Init output buffer to broadcast bias: out[n, o] = bias[o]  (float4)
// ---------------------------------------------------------------------------
__global__ void init_bias_kernel(float4* __restrict__ out,
                                 const float4* __restrict__ bias)
{
    int i = blockIdx.x * 256 + threadIdx.x;
    if (i < N_NODES * (DOUT / 4)) out[i] = bias[i & (DOUT / 4 - 1)];
}

// ---------------------------------------------------------------------------
// Edge kernel: one warp per edge; fp16 gather, fp32 math, red.v4 scatter.
// ---------------------------------------------------------------------------
__global__ __launch_bounds__(256) void edge_kernel(
    const __half* __restrict__ hp,
    const float* __restrict__ pseudo,
    const int* __restrict__ src,
    const int* __restrict__ dst,
    const float* __restrict__ mu,
    const float* __restrict__ inv_sigma,
    const float* __restrict__ pw,
    const float* __restrict__ pb,
    float* __restrict__ out)
{
    const int e = blockIdx.x * 8 + (threadIdx.x >> 5);
    if (e >= N_EDGES) return;
    const int lane = threadIdx.x & 31;

    const int s = src[e];
    const int d = dst[e];

    const float p0 = __ldg(&pseudo[2 * e + 0]);
    const float p1 = __ldg(&pseudo[2 * e + 1]);
    const float u0 = tanhf(p0 * pw[0] + p1 * pw[2] + pb[0]);
    const float u1 = tanhf(p0 * pw[1] + p1 * pw[3] + pb[1]);

    float w[KMIX];
    #pragma unroll
    for (int k = 0; k < KMIX; k++) {
        float d0 = (u0 - mu[2 * k + 0]) * inv_sigma[2 * k + 0];
        float d1 = (u1 - mu[2 * k + 1]) * inv_sigma[2 * k + 1];
        w[k] = __expf(-0.5f * (d0 * d0 + d1 * d1));
    }

    const __half* hpb = hp + (size_t)s * HPW + lane * 4;

    float4 acc = make_float4(0.f, 0.f, 0.f, 0.f);
    #pragma unroll
    for (int k = 0; k < KMIX; k++) {
        uint2 raw = __ldg((const uint2*)(hpb + k * DOUT));
        __half2 h01 = *(__half2*)&raw.x;
        __half2 h23 = *(__half2*)&raw.y;
        float2 f01 = __half22float2(h01);
        float2 f23 = __half22float2(h23);
        acc.x += w[k] * f01.x;
        acc.y += w[k] * f01.y;
        acc.z += w[k] * f23.x;
        acc.w += w[k] * f23.y;
    }

    float* o = out + (size_t)d * DOUT + lane * 4;
    asm volatile("red.global.add.v4.f32 [%0], {%1, %2, %3, %4};"
                 :: "l"(o), "f"(acc.x), "f"(acc.y), "f"(acc.z), "f"(acc.w)
                 : "memory");
}

// ---------------------------------------------------------------------------
// Launch: 3 layers, each = GEMM -> bias-init -> edge scatter
// ---------------------------------------------------------------------------
extern "C" void kernel_launch(void* const* d_in, const int* in_sizes, int n_in,
                              void* d_out, int out_size)
{
    const float* features = (const float*)d_in[0];
    const float* pseudo   = (const float*)d_in[1];
    const int*   src      = (const int*)d_in[2];
    const int*   dst      = (const int*)d_in[3];

    const float* fc_w[3];
    const float* mu[3];
    const float* is[3];
    const float* bias[3];
    const float* pw[3];
    const float* pb[3];
    for (int l = 0; l < 3; l++) {
        fc_w[l] = (const float*)d_in[4 + 6 * l + 0];
        mu[l]   = (const float*)d_in[4 + 6 * l + 1];
        is[l]   = (const float*)d_in[4 + 6 * l + 2];
        bias[l] = (const float*)d_in[4 + 6 * l + 3];
        pw[l]   = (const float*)d_in[4 + 6 * l + 4];
        pb[l]   = (const float*)d_in[4 + 6 * l + 5];
    }

    __half* hp; float* h0; float* h1;
    cudaGetSymbolAddress((void**)&hp, g_hp);
    cudaGetSymbolAddress((void**)&h0, g_h0);
    cudaGetSymbolAddress((void**)&h1, g_h1);

    const float* layer_in[3]  = { features, h0, h1 };
    float*       layer_out[3] = { h0, h1, (float*)d_out };
    const int    layer_k[3]   = { IN_FEATS, DOUT, DOUT };

    dim3 gemm_grid(HPW / TBN, (N_NODES + TBM - 1) / TBM);
    const int init_blocks = (N_NODES * (DOUT / 4) + 255) / 256;
    const int edge_blocks = (N_EDGES + 7) / 8;

    for (int l = 0; l < 3; l++) {
        gemm_tf32_kernel<<<gemm_grid, 256>>>(layer_in[l], fc_w[l], hp,
                                             N_NODES, layer_k[l], HPW);
        init_bias_kernel<<<init_blocks, 256>>>((float4*)layer_out[l],
                                               (const float4*)bias[l]);
        edge_kernel<<<edge_blocks, 256>>>(hp, pseudo, src, dst,
                                          mu[l], is[l], pw[l], pb[l],
                                          layer_out[l]);
    }
}

// round 13
// speedup vs baseline: 1.7311x; 1.0047x over previous
#include <cuda_runtime.h>
#include <cuda_fp16.h>
#include <mma.h>

using namespace nvcuda;

#define N_NODES 20000
#define N_EDGES 320000
#define IN_FEATS 64
#define DOUT 128
#define KMIX 4
#define HPW (KMIX * DOUT)   // 512

// Scratch (no allocation allowed)
__device__ __half g_hp[N_NODES * HPW];   // 20.48 MB (fp16) — L2-resident
__device__ float  g_h0[N_NODES * DOUT];  // 10.24 MB
__device__ float  g_h1[N_NODES * DOUT];  // 10.24 MB

// ---------------------------------------------------------------------------
// tf32 tensor-core GEMM with 2-stage cp.async pipeline.
// C[M,N] = A[M,Kdim] @ B[Kdim,N], fp32 in, fp32 accum, fp16 out.
// Block tile 128x128, BK=16. 8 warps: 4x2, each warp 32x64 (2x4 frags).
// ---------------------------------------------------------------------------
#define TBM 128
#define TBN 128
#define TBK 16
#define A_LD 20    // 16 + 4 pad (80 B row stride, 16B aligned)
#define B_LD 132   // 128 + 4 pad (528 B row stride, 16B aligned)

__device__ __forceinline__ void cp_async16(void* dst, const void* src,
                                           int src_bytes)
{
    unsigned int sdst = (unsigned int)__cvta_generic_to_shared(dst);
    asm volatile("cp.async.cg.shared.global [%0], [%1], 16, %2;"
                 :: "r"(sdst), "l"(src), "r"(src_bytes));
}

__global__ __launch_bounds__(256) void gemm_tf32_kernel(
    const float* __restrict__ A, const float* __restrict__ B,
    __half* __restrict__ C, int M, int Kdim, int N)
{
    __shared__ float As[2][TBM][A_LD];   // 2 x 10240 B
    __shared__ float Bs[2][TBK][B_LD];   // 2 x  8448 B

    const int tid = threadIdx.x;
    const int wid = tid >> 5;
    const int lane = tid & 31;
    const int warp_row = wid >> 1;   // 0..3 -> rows 32*warp_row
    const int warp_col = wid & 1;    // 0..1 -> cols 64*warp_col
    const int row0 = blockIdx.y * TBM;
    const int col0 = blockIdx.x * TBN;

    const int ntiles = Kdim / TBK;

    wmma::fragment<wmma::accumulator, 16, 16, 8, float> acc[2][4];
    #pragma unroll
    for (int i = 0; i < 2; i++)
        #pragma unroll
        for (int j = 0; j < 4; j++)
            wmma::fill_fragment(acc[i][j], 0.0f);

    // ---- tile copy via cp.async (each thread: 2 A chunks + 2 B chunks) ----
    // Padding rows: src address CLAMPED in-bounds, src_bytes=0 -> zero-fill.
    auto copy_tile = [&](int buf, int kb) {
        // A: 128 rows x 16 floats = 512 x 16B. f: r=f>>2, c=(f&3)*4
        #pragma unroll
        for (int f = tid; f < 512; f += 256) {
            int r = f >> 2;
            int c = (f & 3) << 2;
            int gr = row0 + r;
            int ga = gr < M ? gr : (M - 1);
            cp_async16(&As[buf][r][c],
                       &A[(size_t)ga * Kdim + kb + c],
                       gr < M ? 16 : 0);
        }
        // B: 16 rows x 128 floats = 512 x 16B. f: r=f>>5, c=(f&31)*4
        #pragma unroll
        for (int f = tid; f < 512; f += 256) {
            int r = f >> 5;
            int c = (f & 31) << 2;
            cp_async16(&Bs[buf][r][c],
                       &B[(size_t)(kb + r) * N + col0 + c], 16);
        }
        asm volatile("cp.async.commit_group;");
    };

    copy_tile(0, 0);

    for (int t = 0; t < ntiles; t++) {
        if (t + 1 < ntiles) {
            copy_tile((t + 1) & 1, (t + 1) * TBK);
            asm volatile("cp.async.wait_group 1;");
        } else {
            asm volatile("cp.async.wait_group 0;");
        }
        __syncthreads();

        const int buf = t & 1;
        #pragma unroll
        for (int kk = 0; kk < TBK / 8; kk++) {
            wmma::fragment<wmma::matrix_a, 16, 16, 8,
                           wmma::precision::tf32, wmma::row_major> af[2];
            wmma::fragment<wmma::matrix_b, 16, 16, 8,
                           wmma::precision::tf32, wmma::row_major> bf[4];
            #pragma unroll
            for (int i = 0; i < 2; i++) {
                wmma::load_matrix_sync(
                    af[i], &As[buf][warp_row * 32 + i * 16][kk * 8], A_LD);
                #pragma unroll
                for (int t2 = 0; t2 < af[i].num_elements; t2++)
                    af[i].x[t2] = wmma::__float_to_tf32(af[i].x[t2]);
            }
            #pragma unroll
            for (int j = 0; j < 4; j++) {
                wmma::load_matrix_sync(
                    bf[j], &Bs[buf][kk * 8][warp_col * 64 + j * 16], B_LD);
                #pragma unroll
                for (int t2 = 0; t2 < bf[j].num_elements; t2++)
                    bf[j].x[t2] = wmma::__float_to_tf32(bf[j].x[t2]);
            }
            #pragma unroll
            for (int i = 0; i < 2; i++)
                #pragma unroll
                for (int j = 0; j < 4; j++)
                    wmma::mma_sync(acc[i][j], af[i], bf[j], acc[i][j]);
        }
        __syncthreads();
    }

    // Epilogue: per-warp 256-float stage (overlaid on As), fp16 uint4 stores
    float* stage = &As[0][0][0] + wid * 256;
    #pragma unroll
    for (int i = 0; i < 2; i++) {
        #pragma unroll
        for (int j = 0; j < 4; j++) {
            wmma::store_matrix_sync(stage, acc[i][j], 16, wmma::mem_row_major);
            __syncwarp();
            int r = lane >> 1;            // 0..15
            int coff = (lane & 1) << 3;   // 0 or 8
            int gr = row0 + warp_row * 32 + i * 16 + r;
            if (gr < M) {
                const float* srow = &stage[r * 16 + coff];
                __half2 h0 = __float22half2_rn(make_float2(srow[0], srow[1]));
                __half2 h1 = __float22half2_rn(make_float2(srow[2], srow[3]));
                __half2 h2 = __float22half2_rn(make_float2(srow[4], srow[5]));
                __half2 h3 = __float22half2_rn(make_float2(srow[6], srow[7]));
                uint4 v;
                v.x = *(unsigned int*)&h0;
                v.y = *(unsigned int*)&h1;
                v.z = *(unsigned int*)&h2;
                v.w = *(unsigned int*)&h3;
                *(uint4*)&C[(size_t)gr * N + col0 + warp_col * 64 + j * 16 + coff] = v;
            }
            __syncwarp();
        }
    }
}

// ---------------------------------------------------------------------------
// Init output buffer to broadcast bias: out[n, o] = bias[o]  (float4)
// ---------------------------------------------------------------------------
__global__ void init_bias_kernel(float4* __restrict__ out,
                                 const float4* __restrict__ bias)
{
    int i = blockIdx.x * 256 + threadIdx.x;
    if (i < N_NODES * (DOUT / 4)) out[i] = bias[i & (DOUT / 4 - 1)];
}

// ---------------------------------------------------------------------------
// Edge kernel: one warp per edge; fp16 gather, fp32 math, red.v4 scatter.
// ---------------------------------------------------------------------------
__global__ __launch_bounds__(256) void edge_kernel(
    const __half* __restrict__ hp,
    const float* __restrict__ pseudo,
    const int* __restrict__ src,
    const int* __restrict__ dst,
    const float* __restrict__ mu,
    const float* __restrict__ inv_sigma,
    const float* __restrict__ pw,
    const float* __restrict__ pb,
    float* __restrict__ out)
{
    const int e = blockIdx.x * 8 + (threadIdx.x >> 5);
    if (e >= N_EDGES) return;
    const int lane = threadIdx.x & 31;

    const int s = src[e];
    const int d = dst[e];

    const float p0 = __ldg(&pseudo[2 * e + 0]);
    const float p1 = __ldg(&pseudo[2 * e + 1]);
    const float u0 = tanhf(p0 * pw[0] + p1 * pw[2] + pb[0]);
    const float u1 = tanhf(p0 * pw[1] + p1 * pw[3] + pb[1]);

    float w[KMIX];
    #pragma unroll
    for (int k = 0; k < KMIX; k++) {
        float d0 = (u0 - mu[2 * k + 0]) * inv_sigma[2 * k + 0];
        float d1 = (u1 - mu[2 * k + 1]) * inv_sigma[2 * k + 1];
        w[k] = __expf(-0.5f * (d0 * d0 + d1 * d1));
    }

    const __half* hpb = hp + (size_t)s * HPW + lane * 4;

    float4 acc = make_float4(0.f, 0.f, 0.f, 0.f);
    #pragma unroll
    for (int k = 0; k < KMIX; k++) {
        uint2 raw = __ldg((const uint2*)(hpb + k * DOUT));
        __half2 h01 = *(__half2*)&raw.x;
        __half2 h23 = *(__half2*)&raw.y;
        float2 f01 = __half22float2(h01);
        float2 f23 = __half22float2(h23);
        acc.x += w[k] * f01.x;
        acc.y += w[k] * f01.y;
        acc.z += w[k] * f23.x;
        acc.w += w[k] * f23.y;
    }

    float* o = out + (size_t)d * DOUT + lane * 4;
    asm volatile("red.global.add.v4.f32 [%0], {%1, %2, %3, %4};"
                 :: "l"(o), "f"(acc.x), "f"(acc.y), "f"(acc.z), "f"(acc.w)
                 : "memory");
}

// ---------------------------------------------------------------------------
// Launch: 3 layers, each = GEMM -> bias-init -> edge scatter
// ---------------------------------------------------------------------------
extern "C" void kernel_launch(void* const* d_in, const int* in_sizes, int n_in,
                              void* d_out, int out_size)
{
    const float* features = (const float*)d_in[0];
    const float* pseudo   = (const float*)d_in[1];
    const int*   src      = (const int*)d_in[2];
    const int*   dst      = (const int*)d_in[3];

    const float* fc_w[3];
    const float* mu[3];
    const float* is[3];
    const float* bias[3];
    const float* pw[3];
    const float* pb[3];
    for (int l = 0; l < 3; l++) {
        fc_w[l] = (const float*)d_in[4 + 6 * l + 0];
        mu[l]   = (const float*)d_in[4 + 6 * l + 1];
        is[l]   = (const float*)d_in[4 + 6 * l + 2];
        bias[l] = (const float*)d_in[4 + 6 * l + 3];
        pw[l]   = (const float*)d_in[4 + 6 * l + 4];
        pb[l]   = (const float*)d_in[4 + 6 * l + 5];
    }

    __half* hp; float* h0; float* h1;
    cudaGetSymbolAddress((void**)&hp, g_hp);
    cudaGetSymbolAddress((void**)&h0, g_h0);
    cudaGetSymbolAddress((void**)&h1, g_h1);

    const float* layer_in[3]  = { features, h0, h1 };
    float*       layer_out[3] = { h0, h1, (float*)d_out };
    const int    layer_k[3]   = { IN_FEATS, DOUT, DOUT };

    dim3 gemm_grid(HPW / TBN, (N_NODES + TBM - 1) / TBM);
    const int init_blocks = (N_NODES * (DOUT / 4) + 255) / 256;
    const int edge_blocks = (N_EDGES + 7) / 8;

    for (int l = 0; l < 3; l++) {
        gemm_tf32_kernel<<<gemm_grid, 256>>>(layer_in[l], fc_w[l], hp,
                                             N_NODES, layer_k[l], HPW);
        init_bias_kernel<<<init_blocks, 256>>>((float4*)layer_out[l],
                                               (const float4*)bias[l]);
        edge_kernel<<<edge_blocks, 256>>>(hp, pseudo, src, dst,
                                          mu[l], is[l], pw[l], pb[l],
                                          layer_out[l]);
    }
}

// round 15
// speedup vs baseline: 1.8661x; 1.0780x over previous
#include <cuda_runtime.h>
#include <cuda_fp16.h>
#include <mma.h>

using namespace nvcuda;

#define N_NODES 20000
#define N_EDGES 320000
#define IN_FEATS 64
#define DOUT 128
#define KMIX 4
#define HPW (KMIX * DOUT)   // 512

// Scratch (no allocation allowed)
__device__ __half g_hp[N_NODES * HPW];   // 20.48 MB (fp16) — L2-resident
__device__ float  g_h0[N_NODES * DOUT];  // 10.24 MB
__device__ float  g_h1[N_NODES * DOUT];  // 10.24 MB

// ---------------------------------------------------------------------------
// tf32 tensor-core GEMM, 2-stage cp.async pipeline, 2 CTAs/SM.
// C[M,N] = A[M,Kdim] @ B[Kdim,N], fp32 in, fp32 accum, fp16 out.
// Block tile 128x128, BK=16. 8 warps: 4x2, each warp 32x64 (2x4 frags).
// ---------------------------------------------------------------------------
#define TBM 128
#define TBN 128
#define TBK 16
#define A_LD 20    // 16 + 4 pad (80 B row stride, 16B aligned)
#define B_LD 132   // 128 + 4 pad (528 B row stride, 16B aligned)

__device__ __forceinline__ void cp_async16(void* dst, const void* src,
                                           int src_bytes)
{
    unsigned int sdst = (unsigned int)__cvta_generic_to_shared(dst);
    asm volatile("cp.async.cg.shared.global [%0], [%1], 16, %2;"
                 :: "r"(sdst), "l"(src), "r"(src_bytes));
}

__global__ __launch_bounds__(256, 2) void gemm_tf32_kernel(
    const float* __restrict__ A, const float* __restrict__ B,
    __half* __restrict__ C, int M, int Kdim, int N)
{
    __shared__ float As[2][TBM][A_LD];   // 2 x 10240 B
    __shared__ float Bs[2][TBK][B_LD];   // 2 x  8448 B

    const int tid = threadIdx.x;
    const int wid = tid >> 5;
    const int lane = tid & 31;
    const int warp_row = wid >> 1;   // 0..3 -> rows 32*warp_row
    const int warp_col = wid & 1;    // 0..1 -> cols 64*warp_col
    const int row0 = blockIdx.y * TBM;
    const int col0 = blockIdx.x * TBN;

    const int ntiles = Kdim / TBK;

    wmma::fragment<wmma::accumulator, 16, 16, 8, float> acc[2][4];
    #pragma unroll
    for (int i = 0; i < 2; i++)
        #pragma unroll
        for (int j = 0; j < 4; j++)
            wmma::fill_fragment(acc[i][j], 0.0f);

    // ---- tile copy via cp.async (each thread: 2 A chunks + 2 B chunks) ----
    // Padding rows: src address clamped in-bounds, src_bytes=0 -> zero-fill.
    auto copy_tile = [&](int buf, int kb) {
        #pragma unroll
        for (int f = tid; f < 512; f += 256) {
            int r = f >> 2;
            int c = (f & 3) << 2;
            int gr = row0 + r;
            int ga = gr < M ? gr : (M - 1);
            cp_async16(&As[buf][r][c],
                       &A[(size_t)ga * Kdim + kb + c],
                       gr < M ? 16 : 0);
        }
        #pragma unroll
        for (int f = tid; f < 512; f += 256) {
            int r = f >> 5;
            int c = (f & 31) << 2;
            cp_async16(&Bs[buf][r][c],
                       &B[(size_t)(kb + r) * N + col0 + c], 16);
        }
        asm volatile("cp.async.commit_group;");
    };

    copy_tile(0, 0);

    for (int t = 0; t < ntiles; t++) {
        if (t + 1 < ntiles) {
            copy_tile((t + 1) & 1, (t + 1) * TBK);
            asm volatile("cp.async.wait_group 1;");
        } else {
            asm volatile("cp.async.wait_group 0;");
        }
        __syncthreads();

        const int buf = t & 1;
        #pragma unroll
        for (int kk = 0; kk < TBK / 8; kk++) {
            wmma::fragment<wmma::matrix_a, 16, 16, 8,
                           wmma::precision::tf32, wmma::row_major> af[2];
            wmma::fragment<wmma::matrix_b, 16, 16, 8,
                           wmma::precision::tf32, wmma::row_major> bf[4];
            #pragma unroll
            for (int i = 0; i < 2; i++) {
                wmma::load_matrix_sync(
                    af[i], &As[buf][warp_row * 32 + i * 16][kk * 8], A_LD);
                #pragma unroll
                for (int t2 = 0; t2 < af[i].num_elements; t2++)
                    af[i].x[t2] = wmma::__float_to_tf32(af[i].x[t2]);
            }
            #pragma unroll
            for (int j = 0; j < 4; j++) {
                wmma::load_matrix_sync(
                    bf[j], &Bs[buf][kk * 8][warp_col * 64 + j * 16], B_LD);
                #pragma unroll
                for (int t2 = 0; t2 < bf[j].num_elements; t2++)
                    bf[j].x[t2] = wmma::__float_to_tf32(bf[j].x[t2]);
            }
            #pragma unroll
            for (int i = 0; i < 2; i++)
                #pragma unroll
                for (int j = 0; j < 4; j++)
                    wmma::mma_sync(acc[i][j], af[i], bf[j], acc[i][j]);
        }
        __syncthreads();
    }

    // Epilogue: per-warp 256-float stage (overlaid on As), fp16 uint4 stores
    float* stage = &As[0][0][0] + wid * 256;
    #pragma unroll
    for (int i = 0; i < 2; i++) {
        #pragma unroll
        for (int j = 0; j < 4; j++) {
            wmma::store_matrix_sync(stage, acc[i][j], 16, wmma::mem_row_major);
            __syncwarp();
            int r = lane >> 1;            // 0..15
            int coff = (lane & 1) << 3;   // 0 or 8
            int gr = row0 + warp_row * 32 + i * 16 + r;
            if (gr < M) {
                const float* srow = &stage[r * 16 + coff];
                __half2 h0 = __float22half2_rn(make_float2(srow[0], srow[1]));
                __half2 h1 = __float22half2_rn(make_float2(srow[2], srow[3]));
                __half2 h2 = __float22half2_rn(make_float2(srow[4], srow[5]));
                __half2 h3 = __float22half2_rn(make_float2(srow[6], srow[7]));
                uint4 v;
                v.x = *(unsigned int*)&h0;
                v.y = *(unsigned int*)&h1;
                v.z = *(unsigned int*)&h2;
                v.w = *(unsigned int*)&h3;
                *(uint4*)&C[(size_t)gr * N + col0 + warp_col * 64 + j * 16 + coff] = v;
            }
            __syncwarp();
        }
    }
}

// ---------------------------------------------------------------------------
// Init output buffer to broadcast bias: out[n, o] = bias[o]  (float4)
// ---------------------------------------------------------------------------
__global__ void init_bias_kernel(float4* __restrict__ out,
                                 const float4* __restrict__ bias)
{
    int i = blockIdx.x * 256 + threadIdx.x;
    if (i < N_NODES * (DOUT / 4)) out[i] = bias[i & (DOUT / 4 - 1)];
}

// ---------------------------------------------------------------------------
// Edge kernel: one warp per edge; fp16 gather, fp32 math, red.v4 scatter.
// ---------------------------------------------------------------------------
__global__ __launch_bounds__(256) void edge_kernel(
    const __half* __restrict__ hp,
    const float* __restrict__ pseudo,
    const int* __restrict__ src,
    const int* __restrict__ dst,
    const float* __restrict__ mu,
    const float* __restrict__ inv_sigma,
    const float* __restrict__ pw,
    const float* __restrict__ pb,
    float* __restrict__ out)
{
    const int e = blockIdx.x * 8 + (threadIdx.x >> 5);
    if (e >= N_EDGES) return;
    const int lane = threadIdx.x & 31;

    const int s = src[e];
    const int d = dst[e];

    const float p0 = __ldg(&pseudo[2 * e + 0]);
    const float p1 = __ldg(&pseudo[2 * e + 1]);
    const float u0 = tanhf(p0 * pw[0] + p1 * pw[2] + pb[0]);
    const float u1 = tanhf(p0 * pw[1] + p1 * pw[3] + pb[1]);

    float w[KMIX];
    #pragma unroll
    for (int k = 0; k < KMIX; k++) {
        float d0 = (u0 - mu[2 * k + 0]) * inv_sigma[2 * k + 0];
        float d1 = (u1 - mu[2 * k + 1]) * inv_sigma[2 * k + 1];
        w[k] = __expf(-0.5f * (d0 * d0 + d1 * d1));
    }

    const __half* hpb = hp + (size_t)s * HPW + lane * 4;

    float4 acc = make_float4(0.f, 0.f, 0.f, 0.f);
    #pragma unroll
    for (int k = 0; k < KMIX; k++) {
        uint2 raw = __ldg((const uint2*)(hpb + k * DOUT));
        __half2 h01 = *(__half2*)&raw.x;
        __half2 h23 = *(__half2*)&raw.y;
        float2 f01 = __half22float2(h01);
        float2 f23 = __half22float2(h23);
        acc.x += w[k] * f01.x;
        acc.y += w[k] * f01.y;
        acc.z += w[k] * f23.x;
        acc.w += w[k] * f23.y;
    }

    float* o = out + (size_t)d * DOUT + lane * 4;
    asm volatile("red.global.add.v4.f32 [%0], {%1, %2, %3, %4};"
                 :: "l"(o), "f"(acc.x), "f"(acc.y), "f"(acc.z), "f"(acc.w)
                 : "memory");
}

// ---------------------------------------------------------------------------
// Launch: 3 layers, each = GEMM -> bias-init -> edge scatter
// ---------------------------------------------------------------------------
extern "C" void kernel_launch(void* const* d_in, const int* in_sizes, int n_in,
                              void* d_out, int out_size)
{
    const float* features = (const float*)d_in[0];
    const float* pseudo   = (const float*)d_in[1];
    const int*   src      = (const int*)d_in[2];
    const int*   dst      = (const int*)d_in[3];

    const float* fc_w[3];
    const float* mu[3];
    const float* is[3];
    const float* bias[3];
    const float* pw[3];
    const float* pb[3];
    for (int l = 0; l < 3; l++) {
        fc_w[l] = (const float*)d_in[4 + 6 * l + 0];
        mu[l]   = (const float*)d_in[4 + 6 * l + 1];
        is[l]   = (const float*)d_in[4 + 6 * l + 2];
        bias[l] = (const float*)d_in[4 + 6 * l + 3];
        pw[l]   = (const float*)d_in[4 + 6 * l + 4];
        pb[l]   = (const float*)d_in[4 + 6 * l + 5];
    }

    __half* hp; float* h0; float* h1;
    cudaGetSymbolAddress((void**)&hp, g_hp);
    cudaGetSymbolAddress((void**)&h0, g_h0);
    cudaGetSymbolAddress((void**)&h1, g_h1);

    const float* layer_in[3]  = { features, h0, h1 };
    float*       layer_out[3] = { h0, h1, (float*)d_out };
    const int    layer_k[3]   = { IN_FEATS, DOUT, DOUT };

    dim3 gemm_grid(HPW / TBN, (N_NODES + TBM - 1) / TBM);
    const int init_blocks = (N_NODES * (DOUT / 4) + 255) / 256;
    const int edge_blocks = (N_EDGES + 7) / 8;

    for (int l = 0; l < 3; l++) {
        gemm_tf32_kernel<<<gemm_grid, 256>>>(layer_in[l], fc_w[l], hp,
                                             N_NODES, layer_k[l], HPW);
        init_bias_kernel<<<init_blocks, 256>>>((float4*)layer_out[l],
                                               (const float4*)bias[l]);
        edge_kernel<<<edge_blocks, 256>>>(hp, pseudo, src, dst,
                                          mu[l], is[l], pw[l], pb[l],
                                          layer_out[l]);
    }
}

// round 17
// speedup vs baseline: 2.4013x; 1.2868x over previous
#include <cuda_runtime.h>
#include <cuda_fp16.h>
#include <mma.h>

using namespace nvcuda;

#define N_NODES 20000
#define N_EDGES 320000
#define IN_FEATS 64
#define DOUT 128
#define KMIX 4
#define HPW (KMIX * DOUT)   // 512

// Scratch (no allocation allowed)
__device__ __half g_hp[N_NODES * HPW];     // 20.48 MB (fp16) — L2-resident
__device__ float  g_h0[N_NODES * DOUT];    // 10.24 MB
__device__ float  g_h1[N_NODES * DOUT];    // 10.24 MB
__device__ __half g_a16[N_NODES * DOUT];   //  5.12 MB (fp16 activations)
__device__ __half g_w16[3][DOUT * HPW];    //  0.39 MB (fp16 weights)

// ---------------------------------------------------------------------------
// f32 -> f16 conversion (vectorized: float4 -> 4 halves)
// ---------------------------------------------------------------------------
__global__ void cvt_f16_kernel(const float4* __restrict__ in,
                               uint2* __restrict__ out, int n4)
{
    int i = blockIdx.x * 256 + threadIdx.x;
    if (i < n4) {
        float4 v = in[i];
        __half2 a = __float22half2_rn(make_float2(v.x, v.y));
        __half2 b = __float22half2_rn(make_float2(v.z, v.w));
        uint2 r;
        r.x = *(unsigned int*)&a;
        r.y = *(unsigned int*)&b;
        out[i] = r;
    }
}

// ---------------------------------------------------------------------------
// fp16 tensor-core GEMM, 2-stage cp.async pipeline, 2 CTAs/SM.
// C[M,N] = A[M,Kdim] @ B[Kdim,N], fp16 in, fp32 accum, fp16 out.
// Block tile 128x128, BK=32. 8 warps: 4x2, each warp 32x64 (2x4 frags).
// ---------------------------------------------------------------------------
#define TBM 128
#define TBN 128
#define TBK 32
#define A_LD 40    // 32 + 8 pad halves (80 B row stride, 16B aligned)
#define B_LD 136   // 128 + 8 pad halves (272 B row stride, 16B aligned)

__device__ __forceinline__ void cp_async16(void* dst, const void* src,
                                           int src_bytes)
{
    unsigned int sdst = (unsigned int)__cvta_generic_to_shared(dst);
    asm volatile("cp.async.cg.shared.global [%0], [%1], 16, %2;"
                 :: "r"(sdst), "l"(src), "r"(src_bytes));
}

__global__ __launch_bounds__(256, 2) void gemm_f16_kernel(
    const __half* __restrict__ A, const __half* __restrict__ B,
    __half* __restrict__ C, int M, int Kdim, int N)
{
    __shared__ __half As[2][TBM][A_LD];   // 2 x 10240 B
    __shared__ __half Bs[2][TBK][B_LD];   // 2 x  8704 B

    const int tid = threadIdx.x;
    const int wid = tid >> 5;
    const int lane = tid & 31;
    const int warp_row = wid >> 1;   // 0..3 -> rows 32*warp_row
    const int warp_col = wid & 1;    // 0..1 -> cols 64*warp_col
    const int row0 = blockIdx.y * TBM;
    const int col0 = blockIdx.x * TBN;

    const int ntiles = Kdim / TBK;

    wmma::fragment<wmma::accumulator, 16, 16, 16, float> acc[2][4];
    #pragma unroll
    for (int i = 0; i < 2; i++)
        #pragma unroll
        for (int j = 0; j < 4; j++)
            wmma::fill_fragment(acc[i][j], 0.0f);

    // ---- tile copy via cp.async ----
    // A: 128 rows x 32 halves = 4 x 16B chunks/row = 512 chunks
    // B:  32 rows x 128 halves = 16 x 16B chunks/row = 512 chunks
    // Padding rows: src address clamped in-bounds, src_bytes=0 -> zero-fill.
    auto copy_tile = [&](int buf, int kb) {
        #pragma unroll
        for (int f = tid; f < 512; f += 256) {
            int r = f >> 2;
            int c = (f & 3) << 3;            // halves
            int gr = row0 + r;
            int ga = gr < M ? gr : (M - 1);
            cp_async16(&As[buf][r][c],
                       &A[(size_t)ga * Kdim + kb + c],
                       gr < M ? 16 : 0);
        }
        #pragma unroll
        for (int f = tid; f < 512; f += 256) {
            int r = f >> 4;
            int c = (f & 15) << 3;           // halves
            cp_async16(&Bs[buf][r][c],
                       &B[(size_t)(kb + r) * N + col0 + c], 16);
        }
        asm volatile("cp.async.commit_group;");
    };

    copy_tile(0, 0);

    for (int t = 0; t < ntiles; t++) {
        if (t + 1 < ntiles) {
            copy_tile((t + 1) & 1, (t + 1) * TBK);
            asm volatile("cp.async.wait_group 1;");
        } else {
            asm volatile("cp.async.wait_group 0;");
        }
        __syncthreads();

        const int buf = t & 1;
        #pragma unroll
        for (int kk = 0; kk < TBK / 16; kk++) {
            wmma::fragment<wmma::matrix_a, 16, 16, 16, __half,
                           wmma::row_major> af[2];
            wmma::fragment<wmma::matrix_b, 16, 16, 16, __half,
                           wmma::row_major> bf[4];
            #pragma unroll
            for (int i = 0; i < 2; i++)
                wmma::load_matrix_sync(
                    af[i], &As[buf][warp_row * 32 + i * 16][kk * 16], A_LD);
            #pragma unroll
            for (int j = 0; j < 4; j++)
                wmma::load_matrix_sync(
                    bf[j], &Bs[buf][kk * 16][warp_col * 64 + j * 16], B_LD);
            #pragma unroll
            for (int i = 0; i < 2; i++)
                #pragma unroll
                for (int j = 0; j < 4; j++)
                    wmma::mma_sync(acc[i][j], af[i], bf[j], acc[i][j]);
        }
        __syncthreads();
    }

    // Epilogue: per-warp 256-float stage (overlaid on As), fp16 uint4 stores
    float* stage = (float*)&As[0][0][0] + wid * 256;
    #pragma unroll
    for (int i = 0; i < 2; i++) {
        #pragma unroll
        for (int j = 0; j < 4; j++) {
            wmma::store_matrix_sync(stage, acc[i][j], 16, wmma::mem_row_major);
            __syncwarp();
            int r = lane >> 1;            // 0..15
            int coff = (lane & 1) << 3;   // 0 or 8
            int gr = row0 + warp_row * 32 + i * 16 + r;
            if (gr < M) {
                const float* srow = &stage[r * 16 + coff];
                __half2 h0 = __float22half2_rn(make_float2(srow[0], srow[1]));
                __half2 h1 = __float22half2_rn(make_float2(srow[2], srow[3]));
                __half2 h2 = __float22half2_rn(make_float2(srow[4], srow[5]));
                __half2 h3 = __float22half2_rn(make_float2(srow[6], srow[7]));
                uint4 v;
                v.x = *(unsigned int*)&h0;
                v.y = *(unsigned int*)&h1;
                v.z = *(unsigned int*)&h2;
                v.w = *(unsigned int*)&h3;
                *(uint4*)&C[(size_t)gr * N + col0 + warp_col * 64 + j * 16 + coff] = v;
            }
            __syncwarp();
        }
    }
}

// ---------------------------------------------------------------------------
// Init output buffer to broadcast bias: out[n, o] = bias[o]  (float4)
// ---------------------------------------------------------------------------
__global__ void init_bias_kernel(float4* __restrict__ out,
                                 const float4* __restrict__ bias)
{
    int i = blockIdx.x * 256 + threadIdx.x;
    if (i < N_NODES * (DOUT / 4)) out[i] = bias[i & (DOUT / 4 - 1)];
}

// ---------------------------------------------------------------------------
// Edge kernel: one warp per edge; fp16 gather, fp32 math, red.v4 scatter.
// ---------------------------------------------------------------------------
__global__ __launch_bounds__(256) void edge_kernel(
    const __half* __restrict__ hp,
    const float* __restrict__ pseudo,
    const int* __restrict__ src,
    const int* __restrict__ dst,
    const float* __restrict__ mu,
    const float* __restrict__ inv_sigma,
    const float* __restrict__ pw,
    const float* __restrict__ pb,
    float* __restrict__ out)
{
    const int e = blockIdx.x * 8 + (threadIdx.x >> 5);
    if (e >= N_EDGES) return;
    const int lane = threadIdx.x & 31;

    const int s = src[e];
    const int d = dst[e];

    const float p0 = __ldg(&pseudo[2 * e + 0]);
    const float p1 = __ldg(&pseudo[2 * e + 1]);
    const float u0 = tanhf(p0 * pw[0] + p1 * pw[2] + pb[0]);
    const float u1 = tanhf(p0 * pw[1] + p1 * pw[3] + pb[1]);

    float w[KMIX];
    #pragma unroll
    for (int k = 0; k < KMIX; k++) {
        float d0 = (u0 - mu[2 * k + 0]) * inv_sigma[2 * k + 0];
        float d1 = (u1 - mu[2 * k + 1]) * inv_sigma[2 * k + 1];
        w[k] = __expf(-0.5f * (d0 * d0 + d1 * d1));
    }

    const __half* hpb = hp + (size_t)s * HPW + lane * 4;

    float4 acc = make_float4(0.f, 0.f, 0.f, 0.f);
    #pragma unroll
    for (int k = 0; k < KMIX; k++) {
        uint2 raw = __ldg((const uint2*)(hpb + k * DOUT));
        __half2 h01 = *(__half2*)&raw.x;
        __half2 h23 = *(__half2*)&raw.y;
        float2 f01 = __half22float2(h01);
        float2 f23 = __half22float2(h23);
        acc.x += w[k] * f01.x;
        acc.y += w[k] * f01.y;
        acc.z += w[k] * f23.x;
        acc.w += w[k] * f23.y;
    }

    float* o = out + (size_t)d * DOUT + lane * 4;
    asm volatile("red.global.add.v4.f32 [%0], {%1, %2, %3, %4};"
                 :: "l"(o), "f"(acc.x), "f"(acc.y), "f"(acc.z), "f"(acc.w)
                 : "memory");
}

// ---------------------------------------------------------------------------
// Launch: convert weights once; per layer: cvt act -> GEMM -> init -> edge
// ---------------------------------------------------------------------------
extern "C" void kernel_launch(void* const* d_in, const int* in_sizes, int n_in,
                              void* d_out, int out_size)
{
    const float* features = (const float*)d_in[0];
    const float* pseudo   = (const float*)d_in[1];
    const int*   src      = (const int*)d_in[2];
    const int*   dst      = (const int*)d_in[3];

    const float* fc_w[3];
    const float* mu[3];
    const float* is[3];
    const float* bias[3];
    const float* pw[3];
    const float* pb[3];
    for (int l = 0; l < 3; l++) {
        fc_w[l] = (const float*)d_in[4 + 6 * l + 0];
        mu[l]   = (const float*)d_in[4 + 6 * l + 1];
        is[l]   = (const float*)d_in[4 + 6 * l + 2];
        bias[l] = (const float*)d_in[4 + 6 * l + 3];
        pw[l]   = (const float*)d_in[4 + 6 * l + 4];
        pb[l]   = (const float*)d_in[4 + 6 * l + 5];
    }

    __half* hp; float* h0; float* h1; __half* a16; __half* w16;
    cudaGetSymbolAddress((void**)&hp, g_hp);
    cudaGetSymbolAddress((void**)&h0, g_h0);
    cudaGetSymbolAddress((void**)&h1, g_h1);
    cudaGetSymbolAddress((void**)&a16, g_a16);
    cudaGetSymbolAddress((void**)&w16, g_w16);

    const float* layer_in[3]  = { features, h0, h1 };
    float*       layer_out[3] = { h0, h1, (float*)d_out };
    const int    layer_k[3]   = { IN_FEATS, DOUT, DOUT };

    // Convert weights to fp16 (w16 + l * DOUT*HPW)
    for (int l = 0; l < 3; l++) {
        int n4 = layer_k[l] * HPW / 4;
        cvt_f16_kernel<<<(n4 + 255) / 256, 256>>>(
            (const float4*)fc_w[l], (uint2*)(w16 + (size_t)l * DOUT * HPW), n4);
    }

    dim3 gemm_grid(HPW / TBN, (N_NODES + TBM - 1) / TBM);
    const int init_blocks = (N_NODES * (DOUT / 4) + 255) / 256;
    const int edge_blocks = (N_EDGES + 7) / 8;

    for (int l = 0; l < 3; l++) {
        int n4a = N_NODES * layer_k[l] / 4;
        cvt_f16_kernel<<<(n4a + 255) / 256, 256>>>(
            (const float4*)layer_in[l], (uint2*)a16, n4a);
        gemm_f16_kernel<<<gemm_grid, 256>>>(
            a16, w16 + (size_t)l * DOUT * HPW, hp,
            N_NODES, layer_k[l], HPW);
        init_bias_kernel<<<init_blocks, 256>>>((float4*)layer_out[l],
                                               (const float4*)bias[l]);
        edge_kernel<<<edge_blocks, 256>>>(hp, pseudo, src, dst,
                                          mu[l], is[l], pw[l], pb[l],
                                          layer_out[l]);
    }
}